// round 7
// baseline (speedup 1.0000x reference)
#include <cuda_runtime.h>
#include <math.h>

#define TOTAL_PTS   172032
#define NBLK        1344         // blocks; 128 threads x 1 pt = 128 pts/block
#define BLKS_PER_IMG 168         // 21504 / 128
#define INF_A       1.0e8f
#define NCLS        20
#define LN2_075     0.5198603854199589f   // 0.75 * ln(2)

__device__ float4   g_part[NBLK];
__device__ unsigned g_count = 0;

__device__ __forceinline__ float4 warp_red(float4 a) {
    #pragma unroll
    for (int off = 16; off > 0; off >>= 1) {
        a.x += __shfl_down_sync(0xffffffffu, a.x, off);
        a.y += __shfl_down_sync(0xffffffffu, a.y, off);
        a.z += __shfl_down_sync(0xffffffffu, a.z, off);
        a.w += __shfl_down_sync(0xffffffffu, a.w, off);
    }
    return a;
}

__global__ __launch_bounds__(128) void k_fused(
    const float* __restrict__ cls0, const float* __restrict__ cls1, const float* __restrict__ cls2,
    const float* __restrict__ reg0, const float* __restrict__ reg1, const float* __restrict__ reg2,
    const float* __restrict__ ctr0, const float* __restrict__ ctr1, const float* __restrict__ ctr2,
    const float* __restrict__ boxes, const int* __restrict__ labels,
    float* __restrict__ out)
{
    __shared__ float4 sbox[32];
    __shared__ float  sarea[32];
    __shared__ int    slab[32];
    __shared__ int    s_n;
    __shared__ float4 sw[4];
    __shared__ bool   s_last;

    const int tid = threadIdx.x;
    const int bid = blockIdx.x;

    // ---- target-side (batch-major) block-uniform decode ----
    const int b_img = bid / BLKS_PER_IMG;
    const int pblk  = (bid - b_img * BLKS_PER_IMG) << 7;   // point offset in image

    int lv, base, Wsh; float s;
    if (pblk < 16384)      { lv = 0; base = 0;     Wsh = 7; s = 4.0f;  }
    else if (pblk < 20480) { lv = 1; base = 16384; Wsh = 6; s = 8.0f;  }
    else                   { lv = 2; base = 20480; Wsh = 5; s = 16.0f; }

    const int p0 = pblk + tid - base;            // level-local point index
    const int hh = p0 >> Wsh;
    const int ww = p0 & ((1 << Wsh) - 1);
    const float x = ww * s + 0.5f * s;
    const float y = hh * s + 0.5f * s;

    // block y-range for culling (level 0: single row -> exact)
    const int lo_blk = pblk - base;
    const float ymin_blk = (float)(lo_blk >> Wsh) * s + 0.5f * s;
    const float ymax_blk = (float)((lo_blk + 127) >> Wsh) * s + 0.5f * s;

    // ---- prediction-side (level-major) block-uniform decode ----
    const int j0 = bid << 7;
    int HW, b_f, pix;
    const float *cb, *rb, *ob;
    if (j0 < 131072)      { HW = 16384; b_f = j0 >> 14;            pix = j0 & 16383;           cb = cls0; rb = reg0; ob = ctr0; }
    else if (j0 < 163840) { HW = 4096;  b_f = (j0 - 131072) >> 12; pix = (j0 - 131072) & 4095; cb = cls1; rb = reg1; ob = ctr1; }
    else                  { HW = 1024;  b_f = (j0 - 163840) >> 10; pix = (j0 - 163840) & 1023; cb = cls2; rb = reg2; ob = ctr2; }
    pix += tid;

    // ---- PREFETCH: all global loads issued up front (25 x LDG.32 in flight) ----
    const float* cptr = cb + (size_t)(b_f * NCLS) * HW + pix;
    const float* rp   = rb + (size_t)(b_f * 4) * HW + pix;
    const float* op   = ob + (size_t)b_f * HW + pix;

    float v[NCLS];
    #pragma unroll
    for (int c = 0; c < NCLS; c++)
        v[c] = cptr[(size_t)c * HW];
    float rg[4];
    #pragma unroll
    for (int k = 0; k < 4; k++)
        rg[k] = rp[(size_t)k * HW];
    const float oc = *op;

    // ---- box cull + stable compaction (warp 0 only) ----
    if (tid < 32) {
        float4 bb = reinterpret_cast<const float4*>(boxes)[b_img * 32 + tid];
        const float bw = bb.z - bb.x, bh = bb.w - bb.y;
        // y-overlap with block rows (point needs by0 < y < by1)
        bool keep = (bb.y < ymax_blk) & (bb.w > ymin_blk);
        // level feasibility: interior point has mx in [max(w,h)/2, max(w,h))
        if (lv == 0)      keep = keep & (bw <= 128.0f) & (bh <= 128.0f);
        else if (lv == 1) keep = keep & ((bw >= 64.0f)  | (bh >= 64.0f));
        else              keep = keep & ((bw >= 128.0f) | (bh >= 128.0f));
        const unsigned m = __ballot_sync(0xffffffffu, keep);
        if (keep) {
            const int idx = __popc(m & ((1u << tid) - 1u));   // stable -> order preserved
            sbox[idx]  = bb;
            sarea[idx] = bw * bh;
            slab[idx]  = labels[b_img * 32 + tid];
        }
        if (tid == 0) s_n = __popc(m);
    }
    __syncthreads();
    const int nbox = s_n;

    // ---- box assignment over compacted survivors ----
    float best = INF_A;
    int   bi   = 0;
    for (int m = 0; m < nbox; m++) {
        const float4 bb = sbox[m];
        const float l  = x - bb.x;
        const float t  = y - bb.y;
        const float r  = bb.z - x;
        const float bo = bb.w - y;
        const float mn = fminf(fminf(l, t), fminf(r, bo));
        const float mx = fmaxf(fmaxf(l, t), fmaxf(r, bo));
        bool ok;
        if (lv == 0)      ok = (mn > 0.0f) & (mx <= 64.0f);
        else if (lv == 1) ok = (mn > 0.0f) & (mx >= 64.0f) & (mx <= 128.0f);
        else              ok = (mn > 0.0f) & (mx >= 128.0f);
        const float a = sarea[m];
        if (ok & (a < best)) { best = a; bi = m; }
    }
    const bool pos   = best < INF_A;
    const int  label = pos ? slab[bi] : -1;

    // ---- focal loss on prefetched registers ----
    float fsum = 0.0f;
    float maxx = -INF_A;
    #pragma unroll
    for (int c = 0; c < NCLS; c++) {
        const float xx = v[c];
        maxx = fmaxf(maxx, xx);
        const float E  = __expf(xx);
        const float u  = 1.0f + E;
        const float rc = __fdividef(1.0f, u);
        const float pp = E * rc;
        fsum += __log2f(u) * (pp * pp);   // scaled by 0.75*ln2 after loop
    }

    // ---- per-point epilogue ----
    float4 acc = make_float4(0.f, 0.f, 0.f, 0.f);
    {
        float f = fsum * LN2_075;
        if (pos) {
            // focal correction for the hit class (reload logit; L1/L2 hit)
            const float xl = cptr[(size_t)label * HW];
            const float E  = __expf(xl);
            const float u  = 1.0f + E;
            const float rc = __fdividef(1.0f, u);
            const float pp = E * rc;
            const float sp = __logf(u);
            f += 0.25f * (sp - xl) * rc * rc - 0.75f * sp * pp * pp;
            acc.x = f;
            acc.w = 1.0f;

            // targets for winning box
            const float4 wb = sbox[bi];
            const float tl = x - wb.x, tt = y - wb.y, tr = wb.z - x, tb = wb.w - y;
            const float lrmin = fminf(tl, tr), lrmax = fmaxf(tl, tr);
            const float tbmin = fminf(tt, tb), tbmax = fmaxf(tt, tb);
            const float ratio = __fdividef(lrmin, fmaxf(lrmax, 1e-12f)) *
                                __fdividef(tbmin, fmaxf(tbmax, 1e-12f));
            const float ctr_t = sqrtf(fmaxf(ratio, 0.0f));

            // GIoU from prefetched reg planes
            const float pl  = rg[0];
            const float pt2 = rg[1];
            const float pr  = rg[2];
            const float pb  = rg[3];
            const float t_area = (tl + tr) * (tt + tb);
            const float p_area = (pl + pr) * (pt2 + pb);
            const float w_i = fminf(pl, tl) + fminf(pr, tr);
            const float h_i = fminf(pb, tb) + fminf(pt2, tt);
            const float a_i = w_i * h_i;
            const float a_u = t_area + p_area - a_i;
            const float iou = __fdividef(a_i + 1.0f, a_u + 1.0f);
            const float gw  = fmaxf(pl, tl) + fmaxf(pr, tr);
            const float gh  = fmaxf(pb, tb) + fmaxf(pt2, tt);
            const float ac  = gw * gh;
            acc.y = (1.0f - (iou - __fdividef(ac - a_u, ac))) * ctr_t;

            // centerness BCE
            const float e2 = __expf(-fabsf(oc));
            acc.z = fmaxf(oc, 0.0f) + __logf(1.0f + e2) - oc * ctr_t;
        } else {
            // ignore weight: max sigmoid > 0.3  <=>  max logit > ln(3/7)
            if (maxx <= -0.8472978603872037f) acc.x = f;
        }
    }

    // ---- block reduction (4 warps) -> per-block partial ----
    acc = warp_red(acc);
    if ((tid & 31) == 0) sw[tid >> 5] = acc;
    __syncthreads();
    if (tid == 0) {
        float4 a0 = sw[0], a1 = sw[1], a2 = sw[2], a3 = sw[3];
        g_part[bid] = make_float4(a0.x + a1.x + a2.x + a3.x,
                                  a0.y + a1.y + a2.y + a3.y,
                                  a0.z + a1.z + a2.z + a3.z,
                                  a0.w + a1.w + a2.w + a3.w);
    }

    // ---- last block finalizes ----
    if (tid == 0) {
        __threadfence();
        unsigned old = atomicAdd(&g_count, 1u);
        s_last = (old == (unsigned)(gridDim.x - 1));
    }
    __syncthreads();
    if (!s_last) return;
    __threadfence();

    float4 a = make_float4(0.f, 0.f, 0.f, 0.f);
    for (int i = tid; i < NBLK; i += 128) {
        const float4* pp = &g_part[i];
        float4 vv;
        asm volatile("ld.global.cg.v4.f32 {%0,%1,%2,%3}, [%4];"
                     : "=f"(vv.x), "=f"(vv.y), "=f"(vv.z), "=f"(vv.w) : "l"(pp));
        a.x += vv.x; a.y += vv.y; a.z += vv.z; a.w += vv.w;
    }
    a = warp_red(a);
    if ((tid & 31) == 0) sw[tid >> 5] = a;
    __syncthreads();
    if (tid == 0) {
        float4 t0 = sw[0], t1 = sw[1], t2 = sw[2], t3 = sw[3];
        float sx = t0.x + t1.x + t2.x + t3.x;
        float sy = t0.y + t1.y + t2.y + t3.y;
        float sz = t0.z + t1.z + t2.z + t3.z;
        float np = t0.w + t1.w + t2.w + t3.w;
        float inv = __fdividef(1.0f, fmaxf(np, 1.0f));
        out[0] = sx * inv;
        out[1] = sy * inv;
        out[2] = sz * inv;
        g_count = 0;   // reset for next graph replay
    }
}

extern "C" void kernel_launch(void* const* d_in, const int* in_sizes, int n_in,
                              void* d_out, int out_size) {
    const float *cls0, *cls1, *cls2, *reg0, *reg1, *reg2, *ctr0, *ctr1, *ctr2;
    if (in_sizes[1] == 655360) {   // reference-signature order
        cls0 = (const float*)d_in[0]; cls1 = (const float*)d_in[1]; cls2 = (const float*)d_in[2];
        reg0 = (const float*)d_in[3]; reg1 = (const float*)d_in[4]; reg2 = (const float*)d_in[5];
        ctr0 = (const float*)d_in[6]; ctr1 = (const float*)d_in[7]; ctr2 = (const float*)d_in[8];
    } else {                       // setup_inputs dict order
        cls0 = (const float*)d_in[0]; reg0 = (const float*)d_in[1]; ctr0 = (const float*)d_in[2];
        cls1 = (const float*)d_in[3]; reg1 = (const float*)d_in[4]; ctr1 = (const float*)d_in[5];
        cls2 = (const float*)d_in[6]; reg2 = (const float*)d_in[7]; ctr2 = (const float*)d_in[8];
    }
    const float* boxes  = (const float*)d_in[9];
    const int*   labels = (const int*)d_in[10];

    k_fused<<<NBLK, 128>>>(cls0, cls1, cls2, reg0, reg1, reg2,
                           ctr0, ctr1, ctr2, boxes, labels, (float*)d_out);
}